// round 8
// baseline (speedup 1.0000x reference)
#include <cuda_runtime.h>
#include <cuda_bf16.h>

// 3D RoPE apply:
//   x: (1, S, N=16, D=128) fp32, S = f*h*w (= 32760)
//   freqs_cos/sin: (1024, 64) fp32, cols [0,22)=F, [22,43)=H, [43,64)=W
//   seq pos s -> (fi, hi, wi); pair c: row = fi (c<22) | hi (c<43) | wi
//   out pair: (xr*cos - xi*sin, xr*sin + xi*cos)
//
// R6: no smem, no barrier. Each thread loads its own 4 table values per
// position directly (L1/L2-resident rows). Streaming hints (__ldcs/__stcs)
// on the 537 MB x/out streams keep the 512 KB tables L2-resident.

#define NHEADS 16
#define DDIM   128
#define CPAIRS 64                        // D/2
#define VEC_PER_S (NHEADS * DDIM / 4)    // 512 float4 per seq position
#define SPB 4                            // seq positions per block
#define THREADS VEC_PER_S

template <bool GUARD>
__global__ __launch_bounds__(THREADS, 4)
void rope3d_kernel(const float4* __restrict__ x,
                   const float*  __restrict__ fcos,
                   const float*  __restrict__ fsin,
                   const int*    __restrict__ p_h,
                   const int*    __restrict__ p_w,
                   float4*       __restrict__ out,
                   int s_total)
{
    const int s0 = blockIdx.x * SPB;
    const int t  = threadIdx.x;
    const int j  = (t & 31) << 1;        // first channel-pair index (even, 0..62)

    // ---- Front-batch the 4 independent x loads (streaming, evict-first) ----
    const long base = (long)s0 * VEC_PER_S + t;
    float4 v[SPB];
#pragma unroll
    for (int k = 0; k < SPB; ++k) {
        if (!GUARD || (s0 + k < s_total))
            v[k] = __ldcs(&x[base + k * VEC_PER_S]);
    }

    // ---- (fi, hi, wi) for s0, then increment-with-carry per k ----
    const int h  = *p_h;
    const int w  = *p_w;
    const int hw = h * w;
    int fi = s0 / hw;
    int rem = s0 - fi * hw;
    int hi = rem / w;
    int wi = rem - hi * w;

    // which table does pair j / j+1 use?  0=f, 1=h, 2=w
    const int ta = (j  < 22) ? 0 : ((j  < 43) ? 1 : 2);
    const int tb = (j + 1 < 22) ? 0 : ((j + 1 < 43) ? 1 : 2);

#pragma unroll
    for (int k = 0; k < SPB; ++k) {
        if (GUARD && (s0 + k >= s_total)) break;

        const int pos_a = (ta == 0) ? fi : ((ta == 1) ? hi : wi);
        const int pos_b = (tb == 0) ? fi : ((tb == 1) ? hi : wi);

        const float c0  = __ldg(&fcos[pos_a * CPAIRS + j]);
        const float sn0 = __ldg(&fsin[pos_a * CPAIRS + j]);
        const float c1  = __ldg(&fcos[pos_b * CPAIRS + j + 1]);
        const float sn1 = __ldg(&fsin[pos_b * CPAIRS + j + 1]);

        float4 o;
        o.x = fmaf(v[k].x, c0, -v[k].y * sn0);
        o.y = fmaf(v[k].x, sn0,  v[k].y * c0);
        o.z = fmaf(v[k].z, c1, -v[k].w * sn1);
        o.w = fmaf(v[k].z, sn1,  v[k].w * c1);
        __stcs(&out[base + k * VEC_PER_S], o);

        // advance s by one: wi++, carry into hi, then fi
        if (++wi >= w) { wi = 0; if (++hi >= h) { hi = 0; ++fi; } }
    }
}

extern "C" void kernel_launch(void* const* d_in, const int* in_sizes, int n_in,
                              void* d_out, int out_size)
{
    const float4* x    = (const float4*)d_in[0];
    const float*  fcos = (const float*)d_in[1];
    const float*  fsin = (const float*)d_in[2];
    const int* p_h = (const int*)d_in[4];
    const int* p_w = (const int*)d_in[5];
    float4* out = (float4*)d_out;

    const int s_total = in_sizes[0] / (NHEADS * DDIM);   // 32760

    if (s_total % SPB == 0) {
        rope3d_kernel<false><<<s_total / SPB, THREADS>>>(
            x, fcos, fsin, p_h, p_w, out, s_total);
    } else {
        rope3d_kernel<true><<<(s_total + SPB - 1) / SPB, THREADS>>>(
            x, fcos, fsin, p_h, p_w, out, s_total);
    }
}